// round 11
// baseline (speedup 1.0000x reference)
#include <cuda_runtime.h>
#include <math.h>

#define N_VIEWS 512
#define N_MULTI 32
#define MAX_SIFT 2048
#define N_MATCHES 1000000

// Scratch (no device allocation allowed).
__device__ float g_rot[N_VIEWS * 9];   // per-view rotation (pre-scan)
__device__ float g_c33[N_VIEWS * 9];   // scanned rotation products
__device__ float g_c3 [N_VIEWS * 3];   // cumsum of c_3
__device__ int   g_m64;                // 1 if matches buffer is int64, 0 if int32

// ---------------------------------------------------------------------------
// Kernel 0: detect matches dtype. If int64 (values < 2^20, non-negative),
// every odd 32-bit word is a zero hi-word. If int32, odd words are live match
// values (all-zero over 32768 samples ~ impossible).
// ---------------------------------------------------------------------------
__global__ void detect_kernel(const int* __restrict__ mw)
{
    const int lane = threadIdx.x;  // 32 threads
    bool allz = true;
    for (int k = lane; k < 32768; k += 32)
        if (mw[2 * k + 1] != 0) allz = false;
    allz = __all_sync(0xFFFFFFFFu, allz);
    if (lane == 0) g_m64 = allz ? 1 : 0;
}

// ---------------------------------------------------------------------------
// Kernel 1a: Tait-Bryan -> rotation matrices. fp64 trig (MUFU error would
// compound over the 512-deep product). 4 blocks spread the fp64 across SMs.
// ---------------------------------------------------------------------------
__global__ __launch_bounds__(128) void rot_kernel(const float* __restrict__ euler)
{
    const int i = blockIdx.x * 128 + threadIdx.x;
    if (i >= N_VIEWS) return;
    double a = (double)euler[3 * i + 0];
    double b = (double)euler[3 * i + 1];
    double c = (double)euler[3 * i + 2];
    double ca = cos(a), cb = cos(b), cc = cos(c);
    double sa = sin(a), sb = sin(b), sc = sin(c);
    float* R = g_rot + i * 9;
    R[0] = (float)( ca * cc + sa * sb * sc);
    R[1] = (float)(-sa * cb);
    R[2] = (float)(-ca * sc + sa * sb * cc);
    R[3] = (float)( sa * cc - ca * sb * sc);
    R[4] = (float)( ca * cb);
    R[5] = (float)(-sa * sc - ca * sb * cc);
    R[6] = (float)( cb * sc);
    R[7] = (float)( sb);
    R[8] = (float)( cb * cc);
}

// ---------------------------------------------------------------------------
// Kernel 1b: parallel prefix — matmul scan (Hillis-Steele, 9 steps) + cumsum.
// combine(earlier, later) = earlier @ later  == associative_scan(jnp.matmul).
// fp64 accumulation keeps bracketing-order divergence below fp32 rounding.
// ---------------------------------------------------------------------------
__global__ __launch_bounds__(N_VIEWS) void scan_kernel(const float* __restrict__ c_3)
{
    __shared__ double M[N_VIEWS][9];   // 36,864 B
    __shared__ float  T[N_VIEWS][3];   //  6,144 B
    const int i = threadIdx.x;

    #pragma unroll
    for (int k = 0; k < 9; k++) M[i][k] = (double)g_rot[i * 9 + k];
    T[i][0] = c_3[3 * i + 0];
    T[i][1] = c_3[3 * i + 1];
    T[i][2] = c_3[3 * i + 2];
    __syncthreads();

    for (int off = 1; off < N_VIEWS; off <<= 1) {
        double L[9], R[9];
        float t0, t1, t2;
        const bool act = (i >= off);
        if (act) {
            #pragma unroll
            for (int k = 0; k < 9; k++) { L[k] = M[i - off][k]; R[k] = M[i][k]; }
            t0 = T[i - off][0]; t1 = T[i - off][1]; t2 = T[i - off][2];
        }
        __syncthreads();
        if (act) {
            #pragma unroll
            for (int r = 0; r < 3; r++)
                #pragma unroll
                for (int c = 0; c < 3; c++)
                    M[i][3 * r + c] =
                        L[3 * r + 0] * R[0 + c] +
                        L[3 * r + 1] * R[3 + c] +
                        L[3 * r + 2] * R[6 + c];
            T[i][0] += t0; T[i][1] += t1; T[i][2] += t2;
        }
        __syncthreads();
    }

    #pragma unroll
    for (int k = 0; k < 9; k++) g_c33[i * 9 + k] = (float)M[i][k];
    g_c3[i * 3 + 0] = T[i][0];
    g_c3[i * 3 + 1] = T[i][1];
    g_c3[i * 3 + 2] = T[i][2];
}

// ---------------------------------------------------------------------------
// Kernel 2: the HBM kernel (~95% of runtime; DRAM-roofline bound).
// feat[v,s,:] = (sum_m beta[v,m]*pdepth[v,:,m,s] + pdepth0[v,:,s]) @ c33[v] + c3[v]
// Thread owns 4 consecutive s: 99 coalesced float4 loads, 3 float4 stores.
// ---------------------------------------------------------------------------
__global__ __launch_bounds__(256) void feat_kernel(
    const float* __restrict__ beta,
    const float* __restrict__ pdepth,
    const float* __restrict__ pdepth0,
    float* __restrict__ feat)
{
    const int v  = blockIdx.y;
    const int s4 = blockIdx.x * blockDim.x + threadIdx.x;  // float4 idx 0..511

    __shared__ float sb[N_MULTI];
    __shared__ float sR[9];
    __shared__ float st[3];
    if (threadIdx.x < N_MULTI) sb[threadIdx.x] = beta[v * N_MULTI + threadIdx.x];
    if (threadIdx.x < 9)       sR[threadIdx.x] = g_c33[v * 9 + threadIdx.x];
    if (threadIdx.x < 3)       st[threadIdx.x] = g_c3[v * 3 + threadIdx.x];
    __syncthreads();

    const float4* __restrict__ pd  = (const float4*)pdepth;
    const float4* __restrict__ pd0 = (const float4*)pdepth0;
    const size_t S4 = MAX_SIFT / 4;

    float4 a0, a1, a2;
    {
        const size_t vb = (size_t)v * 3;
        a0 = pd0[(vb + 0) * S4 + s4];
        a1 = pd0[(vb + 1) * S4 + s4];
        a2 = pd0[(vb + 2) * S4 + s4];
    }

    float acc[3][4];
    acc[0][0] = a0.x; acc[0][1] = a0.y; acc[0][2] = a0.z; acc[0][3] = a0.w;
    acc[1][0] = a1.x; acc[1][1] = a1.y; acc[1][2] = a1.z; acc[1][3] = a1.w;
    acc[2][0] = a2.x; acc[2][1] = a2.y; acc[2][2] = a2.z; acc[2][3] = a2.w;

    #pragma unroll
    for (int c = 0; c < 3; c++) {
        const size_t base = ((size_t)v * 3 + c) * N_MULTI * S4 + s4;
        #pragma unroll
        for (int m = 0; m < N_MULTI; m++) {
            const float bm = sb[m];
            float4 x = pd[base + (size_t)m * S4];
            acc[c][0] += bm * x.x;
            acc[c][1] += bm * x.y;
            acc[c][2] += bm * x.z;
            acc[c][3] += bm * x.w;
        }
    }

    float out[12];
    #pragma unroll
    for (int k = 0; k < 4; k++) {
        const float x = acc[0][k], y = acc[1][k], z = acc[2][k];
        out[3 * k + 0] = x * sR[0] + y * sR[3] + z * sR[6] + st[0];
        out[3 * k + 1] = x * sR[1] + y * sR[4] + z * sR[7] + st[1];
        out[3 * k + 2] = x * sR[2] + y * sR[5] + z * sR[8] + st[2];
    }
    float4* fo = (float4*)(feat + (size_t)v * MAX_SIFT * 3 + (size_t)s4 * 12);
    fo[0] = make_float4(out[0], out[1], out[2],  out[3]);
    fo[1] = make_float4(out[4], out[5], out[6],  out[7]);
    fo[2] = make_float4(out[8], out[9], out[10], out[11]);
}

// ---------------------------------------------------------------------------
// Kernel 3: pairwise distances. Branches on detected matches dtype.
// feat (12.6 MB) is L2-resident after kernel 2 -> gathers are L2 hits.
// ---------------------------------------------------------------------------
__global__ __launch_bounds__(256) void delta_kernel(
    const int* __restrict__ mw,       // matches as raw 32-bit words
    const float* __restrict__ feat,
    float* __restrict__ delta)
{
    const int i = blockIdx.x * blockDim.x + threadIdx.x;
    if (i >= N_MATCHES) return;

    long long i0, i1;
    if (g_m64) {
        const longlong2 m = ((const longlong2*)mw)[i];
        i0 = m.x; i1 = m.y;
    } else {
        const int2 m = ((const int2*)mw)[i];
        i0 = (long long)m.x; i1 = (long long)m.y;
    }

    const float* p0 = feat + (size_t)i0 * 3;
    const float* p1 = feat + (size_t)i1 * 3;
    const float dx = __ldg(p0 + 0) - __ldg(p1 + 0);
    const float dy = __ldg(p0 + 1) - __ldg(p1 + 1);
    const float dz = __ldg(p0 + 2) - __ldg(p1 + 2);
    delta[i] = sqrtf(dx * dx + dy * dy + dz * dz);
}

// ---------------------------------------------------------------------------
extern "C" void kernel_launch(void* const* d_in, const int* in_sizes, int n_in,
                              void* d_out, int out_size)
{
    const float* euler   = (const float*)d_in[0];  // (512,3)
    const float* c_3     = (const float*)d_in[1];  // (512,1,3)
    const float* beta    = (const float*)d_in[2];  // (512,1,1,32)
    const float* pdepth  = (const float*)d_in[3];  // (512,3,32,2048)
    const float* pdepth0 = (const float*)d_in[4];  // (512,3,1,2048)
    const int*   matches = (const int*)d_in[5];    // (1000000,2) int64 OR int32

    float* feat  = (float*)d_out;                         // 512*2048*3
    float* delta = feat + (size_t)N_VIEWS * MAX_SIFT * 3; // 1000000

    detect_kernel<<<1, 32>>>(matches);
    rot_kernel<<<4, 128>>>(euler);
    scan_kernel<<<1, N_VIEWS>>>(c_3);

    dim3 g2(2, N_VIEWS);
    feat_kernel<<<g2, 256>>>(beta, pdepth, pdepth0, feat);

    delta_kernel<<<(N_MATCHES + 255) / 256, 256>>>(matches, feat, delta);
}

// round 15
// speedup vs baseline: 1.2524x; 1.2524x over previous
#include <cuda_runtime.h>
#include <math.h>

#define N_VIEWS 512
#define N_MULTI 32
#define MAX_SIFT 2048
#define N_MATCHES 1000000

// Scratch (no device allocation allowed).
__device__ float g_rot[N_VIEWS * 9];   // per-view rotation (pre-scan)
__device__ float g_c33[N_VIEWS * 9];   // scanned rotation products
__device__ float g_c3 [N_VIEWS * 3];   // cumsum of c_3
__device__ int   g_m64;                // 1 if matches buffer is int64, 0 if int32

// ---------------------------------------------------------------------------
// Kernel 1: blocks 0-3: Tait-Bryan -> rotation matrices (fp64 trig; MUFU
// error would compound over the 512-deep product). Block 4: matches-dtype
// detection — 2048 odd 32-bit words sampled by 128 threads in ONE memory
// round-trip (the old 1-warp/32K-word version was ~85us of serial latency).
// int64 world: odd words are zero hi-words. int32 world: live values.
// ---------------------------------------------------------------------------
__global__ __launch_bounds__(128) void rot_detect_kernel(
    const float* __restrict__ euler, const int* __restrict__ mw)
{
    if (blockIdx.x == 4) {
        bool any = false;
        #pragma unroll
        for (int r = 0; r < 16; r++) {
            int k = threadIdx.x + r * 128;        // k < 2048
            if (mw[2 * k + 1] != 0) any = true;
        }
        int anynz = __syncthreads_or(any ? 1 : 0);
        if (threadIdx.x == 0) g_m64 = anynz ? 0 : 1;
        return;
    }
    const int i = blockIdx.x * 128 + threadIdx.x;
    double a = (double)euler[3 * i + 0];
    double b = (double)euler[3 * i + 1];
    double c = (double)euler[3 * i + 2];
    double ca = cos(a), cb = cos(b), cc = cos(c);
    double sa = sin(a), sb = sin(b), sc = sin(c);
    float* R = g_rot + i * 9;
    R[0] = (float)( ca * cc + sa * sb * sc);
    R[1] = (float)(-sa * cb);
    R[2] = (float)(-ca * sc + sa * sb * cc);
    R[3] = (float)( sa * cc - ca * sb * sc);
    R[4] = (float)( ca * cb);
    R[5] = (float)(-sa * sc - ca * sb * cc);
    R[6] = (float)( cb * sc);
    R[7] = (float)( sb);
    R[8] = (float)( cb * cc);
}

// ---------------------------------------------------------------------------
// Kernel 2: parallel prefix — matmul scan (Hillis-Steele, 9 steps) + cumsum.
// combine(earlier, later) = earlier @ later  == associative_scan(jnp.matmul).
// fp64 accumulation keeps bracketing-order divergence below fp32 rounding.
// ---------------------------------------------------------------------------
__global__ __launch_bounds__(N_VIEWS) void scan_kernel(const float* __restrict__ c_3)
{
    __shared__ double M[N_VIEWS][9];   // 36,864 B
    __shared__ float  T[N_VIEWS][3];   //  6,144 B
    const int i = threadIdx.x;

    #pragma unroll
    for (int k = 0; k < 9; k++) M[i][k] = (double)g_rot[i * 9 + k];
    T[i][0] = c_3[3 * i + 0];
    T[i][1] = c_3[3 * i + 1];
    T[i][2] = c_3[3 * i + 2];
    __syncthreads();

    for (int off = 1; off < N_VIEWS; off <<= 1) {
        double L[9], R[9];
        float t0, t1, t2;
        const bool act = (i >= off);
        if (act) {
            #pragma unroll
            for (int k = 0; k < 9; k++) { L[k] = M[i - off][k]; R[k] = M[i][k]; }
            t0 = T[i - off][0]; t1 = T[i - off][1]; t2 = T[i - off][2];
        }
        __syncthreads();
        if (act) {
            #pragma unroll
            for (int r = 0; r < 3; r++)
                #pragma unroll
                for (int c = 0; c < 3; c++)
                    M[i][3 * r + c] =
                        L[3 * r + 0] * R[0 + c] +
                        L[3 * r + 1] * R[3 + c] +
                        L[3 * r + 2] * R[6 + c];
            T[i][0] += t0; T[i][1] += t1; T[i][2] += t2;
        }
        __syncthreads();
    }

    #pragma unroll
    for (int k = 0; k < 9; k++) g_c33[i * 9 + k] = (float)M[i][k];
    g_c3[i * 3 + 0] = T[i][0];
    g_c3[i * 3 + 1] = T[i][1];
    g_c3[i * 3 + 2] = T[i][2];
}

// ---------------------------------------------------------------------------
// Kernel 3: the HBM kernel. Measured R11: 72.6us, DRAM 73.2%.
// 3 channel streams interleaved + m unrolled by 2 -> 6 independent LDG.128
// per window to raise MLP and push DRAM% higher.
// ---------------------------------------------------------------------------
__global__ __launch_bounds__(256) void feat_kernel(
    const float* __restrict__ beta,
    const float* __restrict__ pdepth,
    const float* __restrict__ pdepth0,
    float* __restrict__ feat)
{
    const int v  = blockIdx.y;
    const int s4 = blockIdx.x * blockDim.x + threadIdx.x;  // float4 idx 0..511

    __shared__ float sb[N_MULTI];
    __shared__ float sR[9];
    __shared__ float st[3];
    if (threadIdx.x < N_MULTI) sb[threadIdx.x] = beta[v * N_MULTI + threadIdx.x];
    if (threadIdx.x < 9)       sR[threadIdx.x] = g_c33[v * 9 + threadIdx.x];
    if (threadIdx.x < 3)       st[threadIdx.x] = g_c3[v * 3 + threadIdx.x];
    __syncthreads();

    const float4* __restrict__ pd  = (const float4*)pdepth;
    const float4* __restrict__ pd0 = (const float4*)pdepth0;
    const size_t S4 = MAX_SIFT / 4;

    const size_t vb    = (size_t)v * 3;
    const size_t base0 = (vb + 0) * N_MULTI * S4 + s4;
    const size_t base1 = (vb + 1) * N_MULTI * S4 + s4;
    const size_t base2 = (vb + 2) * N_MULTI * S4 + s4;

    float4 a0 = pd0[(vb + 0) * S4 + s4];
    float4 a1 = pd0[(vb + 1) * S4 + s4];
    float4 a2 = pd0[(vb + 2) * S4 + s4];

    float acc[3][4];
    acc[0][0] = a0.x; acc[0][1] = a0.y; acc[0][2] = a0.z; acc[0][3] = a0.w;
    acc[1][0] = a1.x; acc[1][1] = a1.y; acc[1][2] = a1.z; acc[1][3] = a1.w;
    acc[2][0] = a2.x; acc[2][1] = a2.y; acc[2][2] = a2.z; acc[2][3] = a2.w;

    #pragma unroll
    for (int m = 0; m < N_MULTI; m += 2) {
        // 6 independent loads issued before any consuming FMA.
        float4 x0 = pd[base0 + (size_t)m * S4];
        float4 x1 = pd[base1 + (size_t)m * S4];
        float4 x2 = pd[base2 + (size_t)m * S4];
        float4 y0 = pd[base0 + (size_t)(m + 1) * S4];
        float4 y1 = pd[base1 + (size_t)(m + 1) * S4];
        float4 y2 = pd[base2 + (size_t)(m + 1) * S4];
        const float bm = sb[m];
        const float bn = sb[m + 1];
        acc[0][0] += bm * x0.x; acc[0][1] += bm * x0.y; acc[0][2] += bm * x0.z; acc[0][3] += bm * x0.w;
        acc[1][0] += bm * x1.x; acc[1][1] += bm * x1.y; acc[1][2] += bm * x1.z; acc[1][3] += bm * x1.w;
        acc[2][0] += bm * x2.x; acc[2][1] += bm * x2.y; acc[2][2] += bm * x2.z; acc[2][3] += bm * x2.w;
        acc[0][0] += bn * y0.x; acc[0][1] += bn * y0.y; acc[0][2] += bn * y0.z; acc[0][3] += bn * y0.w;
        acc[1][0] += bn * y1.x; acc[1][1] += bn * y1.y; acc[1][2] += bn * y1.z; acc[1][3] += bn * y1.w;
        acc[2][0] += bn * y2.x; acc[2][1] += bn * y2.y; acc[2][2] += bn * y2.z; acc[2][3] += bn * y2.w;
    }

    float out[12];
    #pragma unroll
    for (int k = 0; k < 4; k++) {
        const float x = acc[0][k], y = acc[1][k], z = acc[2][k];
        out[3 * k + 0] = x * sR[0] + y * sR[3] + z * sR[6] + st[0];
        out[3 * k + 1] = x * sR[1] + y * sR[4] + z * sR[7] + st[1];
        out[3 * k + 2] = x * sR[2] + y * sR[5] + z * sR[8] + st[2];
    }
    float4* fo = (float4*)(feat + (size_t)v * MAX_SIFT * 3 + (size_t)s4 * 12);
    fo[0] = make_float4(out[0], out[1], out[2],  out[3]);
    fo[1] = make_float4(out[4], out[5], out[6],  out[7]);
    fo[2] = make_float4(out[8], out[9], out[10], out[11]);
}

// ---------------------------------------------------------------------------
// Kernel 4: pairwise distances. Uniform branch on detected matches dtype.
// feat (12.6 MB) is L2-resident after kernel 3 -> gathers are L2 hits.
// ---------------------------------------------------------------------------
__global__ __launch_bounds__(256) void delta_kernel(
    const int* __restrict__ mw,       // matches as raw 32-bit words
    const float* __restrict__ feat,
    float* __restrict__ delta)
{
    const int i = blockIdx.x * blockDim.x + threadIdx.x;
    if (i >= N_MATCHES) return;

    long long i0, i1;
    if (g_m64) {
        const longlong2 m = ((const longlong2*)mw)[i];
        i0 = m.x; i1 = m.y;
    } else {
        const int2 m = ((const int2*)mw)[i];
        i0 = (long long)m.x; i1 = (long long)m.y;
    }

    const float* p0 = feat + (size_t)i0 * 3;
    const float* p1 = feat + (size_t)i1 * 3;
    const float dx = __ldg(p0 + 0) - __ldg(p1 + 0);
    const float dy = __ldg(p0 + 1) - __ldg(p1 + 1);
    const float dz = __ldg(p0 + 2) - __ldg(p1 + 2);
    delta[i] = sqrtf(dx * dx + dy * dy + dz * dz);
}

// ---------------------------------------------------------------------------
extern "C" void kernel_launch(void* const* d_in, const int* in_sizes, int n_in,
                              void* d_out, int out_size)
{
    const float* euler   = (const float*)d_in[0];  // (512,3)
    const float* c_3     = (const float*)d_in[1];  // (512,1,3)
    const float* beta    = (const float*)d_in[2];  // (512,1,1,32)
    const float* pdepth  = (const float*)d_in[3];  // (512,3,32,2048)
    const float* pdepth0 = (const float*)d_in[4];  // (512,3,1,2048)
    const int*   matches = (const int*)d_in[5];    // (1000000,2) int64 OR int32

    float* feat  = (float*)d_out;                         // 512*2048*3
    float* delta = feat + (size_t)N_VIEWS * MAX_SIFT * 3; // 1000000

    rot_detect_kernel<<<5, 128>>>(euler, matches);
    scan_kernel<<<1, N_VIEWS>>>(c_3);

    dim3 g2(2, N_VIEWS);
    feat_kernel<<<g2, 256>>>(beta, pdepth, pdepth0, feat);

    delta_kernel<<<(N_MATCHES + 255) / 256, 256>>>(matches, feat, delta);
}